// round 5
// baseline (speedup 1.0000x reference)
#include <cuda_runtime.h>
#include <cuda_bf16.h>
#include <math.h>

#define EMB   1024
#define HD    64
#define BATCH 4
#define SEQ   2048
#define ROWS  (BATCH * SEQ)        // 8192
#define TQ    128                  // queries per attention block
#define NQT   (SEQ / TQ)           // 16 query tiles per batch
#define CHUNK 256                  // keys per split-K chunk
#define MAXCH 8                    // max chunks per query tile (qtile 15: 2048/256)
#define TK    16                   // keys per inner SMEM tile
#define NPARTS (BATCH * NQT * MAXCH)   // 512
#define SCALE 0.03125f             // 1/sqrt(1024)

// ---------------- scratch (no allocations allowed) ----------------
__device__ float g_q[ROWS * HD];
__device__ float g_k[ROWS * HD];
__device__ float g_v[ROWS * HD];
__device__ float g_po[(size_t)NPARTS * TQ * HD];   // partial O, layout [part][d][t]
__device__ float g_pm[NPARTS * TQ];                // partial running max
__device__ float g_pl[NPARTS * TQ];                // partial running sum

// ============================================================================
// Kernel 1: QKV projection.  out[m, n] = sum_k x[m,k] * W[k,n]
// BM=64, BN=64, BK=16, 256 threads, 4x4 micro-tile. grid = (ROWS/64, 3).
// ============================================================================
__global__ __launch_bounds__(256) void qkv_kernel(const float* __restrict__ x,
                                                  const float* __restrict__ Wq,
                                                  const float* __restrict__ Wk,
                                                  const float* __restrict__ Wv) {
    const float* W   = (blockIdx.y == 0) ? Wq  : (blockIdx.y == 1 ? Wk  : Wv);
    float*       out = (blockIdx.y == 0) ? g_q : (blockIdx.y == 1 ? g_k : g_v);

    __shared__ float As[16][64];   // [k][m]
    __shared__ float Bs[16][64];   // [k][n]

    const int tid = threadIdx.x;
    const int tx  = tid & 15;      // 0..15 -> N
    const int ty  = tid >> 4;      // 0..15 -> M
    const int m0  = blockIdx.x * 64;

    // A loader: thread -> one float4 of x tile (64 rows x 16 k)
    const int arow = tid >> 2;            // 0..63
    const int ak4  = (tid & 3) * 4;       // 0,4,8,12
    // B loader: thread -> one float4 of W tile (16 k x 64 n)
    const int brow = ty;                  // k within tile
    const int bc4  = tx * 4;              // n

    float acc[4][4];
#pragma unroll
    for (int i = 0; i < 4; ++i)
#pragma unroll
        for (int j = 0; j < 4; ++j) acc[i][j] = 0.f;

    for (int k0 = 0; k0 < EMB; k0 += 16) {
        float4 av = *(const float4*)(x + (size_t)(m0 + arow) * EMB + k0 + ak4);
        float4 bv = *(const float4*)(W + (size_t)(k0 + brow) * HD + bc4);
        As[ak4 + 0][arow] = av.x;
        As[ak4 + 1][arow] = av.y;
        As[ak4 + 2][arow] = av.z;
        As[ak4 + 3][arow] = av.w;
        *(float4*)&Bs[brow][bc4] = bv;
        __syncthreads();

#pragma unroll
        for (int kk = 0; kk < 16; ++kk) {
            float4 a = *(float4*)&As[kk][ty * 4];
            float4 b = *(float4*)&Bs[kk][tx * 4];
            acc[0][0] += a.x * b.x; acc[0][1] += a.x * b.y; acc[0][2] += a.x * b.z; acc[0][3] += a.x * b.w;
            acc[1][0] += a.y * b.x; acc[1][1] += a.y * b.y; acc[1][2] += a.y * b.z; acc[1][3] += a.y * b.w;
            acc[2][0] += a.z * b.x; acc[2][1] += a.z * b.y; acc[2][2] += a.z * b.z; acc[2][3] += a.z * b.w;
            acc[3][0] += a.w * b.x; acc[3][1] += a.w * b.y; acc[3][2] += a.w * b.z; acc[3][3] += a.w * b.w;
        }
        __syncthreads();
    }

#pragma unroll
    for (int i = 0; i < 4; ++i) {
        float4 r = make_float4(acc[i][0], acc[i][1], acc[i][2], acc[i][3]);
        *(float4*)&out[(size_t)(m0 + ty * 4 + i) * HD + tx * 4] = r;
    }
}

// ============================================================================
// Kernel 2: attention partial (flash-style online softmax over one key chunk).
// grid = (MAXCH, NQT, BATCH), 128 threads; thread t owns query row qtile*128+t.
// Writes unnormalized o, running m and l for its chunk.
// ============================================================================
__global__ __launch_bounds__(128) void attn_partial() {
    const int ch    = blockIdx.x;
    const int qtile = blockIdx.y;
    const int b     = blockIdx.z;
    const int nch   = ((qtile + 1) * TQ + CHUNK - 1) / CHUNK;
    if (ch >= nch) return;

    const int t   = threadIdx.x;
    const int qr  = qtile * TQ + t;
    const int row = b * SEQ + qr;

    __shared__ float Ks[TK][HD];
    __shared__ float Vs[TK][HD];

    float q[HD];
    {
        const float4* qp = (const float4*)(g_q + (size_t)row * HD);
#pragma unroll
        for (int i = 0; i < 16; ++i) {
            float4 v4 = qp[i];
            q[4 * i + 0] = v4.x; q[4 * i + 1] = v4.y;
            q[4 * i + 2] = v4.z; q[4 * i + 3] = v4.w;
        }
    }

    float o[HD];
#pragma unroll
    for (int d = 0; d < HD; ++d) o[d] = 0.f;
    float m = __int_as_float(0xff800000);   // -inf
    float l = 0.f;

    const int c0 = ch * CHUNK;
    const int c1 = min(c0 + CHUNK, (qtile + 1) * TQ);

    // loader mapping: 128 threads x 2 float4 each -> 16x64 tile
    const int e0  = t * 2;
    const int lr0 = e0 >> 4,        lc0 = (e0 & 15) * 4;
    const int lr1 = (e0 + 1) >> 4,  lc1 = ((e0 + 1) & 15) * 4;

    for (int k0 = c0; k0 < c1; k0 += TK) {
        __syncthreads();   // previous tile fully consumed before overwrite
        {
            const size_t gb = (size_t)(b * SEQ + k0) * HD;
            *(float4*)&Ks[lr0][lc0] = *(const float4*)(g_k + gb + lr0 * HD + lc0);
            *(float4*)&Ks[lr1][lc1] = *(const float4*)(g_k + gb + lr1 * HD + lc1);
            *(float4*)&Vs[lr0][lc0] = *(const float4*)(g_v + gb + lr0 * HD + lc0);
            *(float4*)&Vs[lr1][lc1] = *(const float4*)(g_v + gb + lr1 * HD + lc1);
        }
        __syncthreads();

        float s[TK];
#pragma unroll
        for (int j = 0; j < TK; ++j) {
            float acc = 0.f;
#pragma unroll
            for (int d4 = 0; d4 < 16; ++d4) {
                float4 kk = *(float4*)&Ks[j][d4 * 4];
                acc += q[4 * d4 + 0] * kk.x + q[4 * d4 + 1] * kk.y
                     + q[4 * d4 + 2] * kk.z + q[4 * d4 + 3] * kk.w;
            }
            s[j] = (k0 + j <= qr) ? acc * SCALE : __int_as_float(0xff800000);
        }

        float mt = m;
#pragma unroll
        for (int j = 0; j < TK; ++j) mt = fmaxf(mt, s[j]);

        const float corr = __expf(m - mt);   // 0 on first tile (m = -inf)
        l *= corr;
#pragma unroll
        for (int d = 0; d < HD; ++d) o[d] *= corr;

#pragma unroll
        for (int j = 0; j < TK; ++j) {
            const float p = __expf(s[j] - mt);
            l += p;
#pragma unroll
            for (int d4 = 0; d4 < 16; ++d4) {
                float4 vv = *(float4*)&Vs[j][d4 * 4];
                o[4 * d4 + 0] += p * vv.x; o[4 * d4 + 1] += p * vv.y;
                o[4 * d4 + 2] += p * vv.z; o[4 * d4 + 3] += p * vv.w;
            }
        }
        m = mt;
    }

    const int part = (b * NQT + qtile) * MAXCH + ch;
    float* po = g_po + (size_t)part * TQ * HD;
#pragma unroll
    for (int d = 0; d < HD; ++d) po[d * TQ + t] = o[d];   // coalesced across t
    g_pm[part * TQ + t] = m;
    g_pl[part * TQ + t] = l;
}

// ============================================================================
// Kernel 3: combine partials across key chunks and normalize.
// grid = (NQT, BATCH), 128 threads; thread t owns query row qtile*128+t.
// ============================================================================
__global__ __launch_bounds__(128) void attn_combine(float* __restrict__ out) {
    const int qtile = blockIdx.x;
    const int b     = blockIdx.y;
    const int t     = threadIdx.x;
    const int nch   = ((qtile + 1) * TQ + CHUNK - 1) / CHUNK;
    const int qr    = qtile * TQ + t;
    const int pbase = (b * NQT + qtile) * MAXCH;

    float M = __int_as_float(0xff800000);
    for (int c = 0; c < nch; ++c)
        M = fmaxf(M, g_pm[(pbase + c) * TQ + t]);

    float L = 0.f;
    float o[HD];
#pragma unroll
    for (int d = 0; d < HD; ++d) o[d] = 0.f;

    for (int c = 0; c < nch; ++c) {
        const int part = pbase + c;
        const float w  = __expf(g_pm[part * TQ + t] - M);
        L += g_pl[part * TQ + t] * w;
        const float* po = g_po + (size_t)part * TQ * HD;
#pragma unroll
        for (int d = 0; d < HD; ++d) o[d] += w * po[d * TQ + t];
    }

    const float inv = 1.f / L;
    float4* op = (float4*)(out + (size_t)(b * SEQ + qr) * HD);
#pragma unroll
    for (int i = 0; i < 16; ++i)
        op[i] = make_float4(o[4 * i + 0] * inv, o[4 * i + 1] * inv,
                            o[4 * i + 2] * inv, o[4 * i + 3] * inv);
}

// ============================================================================
// Launch
// ============================================================================
extern "C" void kernel_launch(void* const* d_in, const int* in_sizes, int n_in,
                              void* d_out, int out_size) {
    (void)in_sizes; (void)n_in; (void)out_size;
    const float* x  = (const float*)d_in[0];
    const float* Wq = (const float*)d_in[1];
    const float* Wk = (const float*)d_in[2];
    const float* Wv = (const float*)d_in[3];
    float* out = (float*)d_out;

    qkv_kernel  <<<dim3(ROWS / 64, 3), 256>>>(x, Wq, Wk, Wv);
    attn_partial<<<dim3(MAXCH, NQT, BATCH), 128>>>();
    attn_combine<<<dim3(NQT, BATCH), 128>>>(out);
}

// round 7
// speedup vs baseline: 1.2822x; 1.2822x over previous
#include <cuda_runtime.h>
#include <cuda_bf16.h>
#include <math.h>
#include <stdint.h>

#define EMB   1024
#define HD    64
#define BATCH 4
#define SEQ   2048
#define ROWS  (BATCH * SEQ)        // 8192
#define TQ    128                  // queries per attention block
#define NQT   (SEQ / TQ)           // 16 query tiles per batch
#define CHUNK 256                  // keys per split-K chunk
#define MAXCH 8
#define TK    16                   // keys per inner SMEM tile
#define NPARTS (BATCH * NQT * MAXCH)   // 512
#define SCALE 0.03125f             // 1/sqrt(1024)

// ---------------- scratch (no allocations allowed) ----------------
__device__ float g_q[ROWS * HD];
__device__ float g_k[ROWS * HD];
__device__ float g_v[ROWS * HD];
__device__ float g_po[(size_t)NPARTS * TQ * HD];   // partial O, layout [part][d][t]
__device__ float g_pm[NPARTS * TQ];
__device__ float g_pl[NPARTS * TQ];

__device__ __forceinline__ float to_tf32(float f) {
    unsigned int u;
    asm("cvt.rna.tf32.f32 %0, %1;" : "=r"(u) : "f"(f));
    return __uint_as_float(u);
}

// ============================================================================
// Kernel 1: QKV projection via tf32 tensor-core mma.
// C[8192x64] = X[8192x1024] @ W[1024x64].  BM=64, BN=64, BK=32.
// 128 threads = 4 warps; warp w owns rows [w*16, w*16+16) x all 64 cols.
// Per 8-k step: 1 A fragment, 8 n-tiles of m16n8k8. grid = (128, 3).
// ============================================================================
__global__ __launch_bounds__(128) void qkv_tf32(const float* __restrict__ x,
                                                const float* __restrict__ Wq,
                                                const float* __restrict__ Wk,
                                                const float* __restrict__ Wv) {
    const float* W   = (blockIdx.y == 0) ? Wq  : (blockIdx.y == 1 ? Wk  : Wv);
    float*       out = (blockIdx.y == 0) ? g_q : (blockIdx.y == 1 ? g_k : g_v);

    __shared__ float Xs[64][36];   // [m][k], pad 4 -> conflict-free frag loads
    __shared__ float Ws[32][68];   // [k][n], pad 4

    const int tid  = threadIdx.x;
    const int lane = tid & 31;
    const int warp = tid >> 5;
    const int g    = lane >> 2;    // groupID 0..7
    const int tig  = lane & 3;     // thread-in-group 0..3
    const int m0   = blockIdx.x * 64;

    // global loader mapping (4 float4 per thread per operand)
    int xr[4], xc[4], wr[4], wc[4];
#pragma unroll
    for (int it = 0; it < 4; ++it) {
        int idx = it * 128 + tid;
        xr[it] = idx >> 3;  xc[it] = (idx & 7)  * 4;   // X tile 64x32
        wr[it] = idx >> 4;  wc[it] = (idx & 15) * 4;   // W tile 32x64
    }

    float c[8][4];
#pragma unroll
    for (int nt = 0; nt < 8; ++nt)
#pragma unroll
        for (int i = 0; i < 4; ++i) c[nt][i] = 0.f;

    float4 px[4], pw[4];

    // preload tile k0=0
#pragma unroll
    for (int it = 0; it < 4; ++it) {
        px[it] = *(const float4*)(x + (size_t)(m0 + xr[it]) * EMB + xc[it]);
        pw[it] = *(const float4*)(W + (size_t)(wr[it]) * HD + wc[it]);
    }
#pragma unroll
    for (int it = 0; it < 4; ++it) {
        float4 v = px[it];
        *(float4*)&Xs[xr[it]][xc[it]] =
            make_float4(to_tf32(v.x), to_tf32(v.y), to_tf32(v.z), to_tf32(v.w));
        v = pw[it];
        *(float4*)&Ws[wr[it]][wc[it]] =
            make_float4(to_tf32(v.x), to_tf32(v.y), to_tf32(v.z), to_tf32(v.w));
    }
    __syncthreads();

    const int mrow = warp * 16;

    for (int k0 = 0; k0 < EMB; k0 += 32) {
        const bool has_next = (k0 + 32 < EMB);
        if (has_next) {
#pragma unroll
            for (int it = 0; it < 4; ++it) {
                px[it] = *(const float4*)(x + (size_t)(m0 + xr[it]) * EMB + k0 + 32 + xc[it]);
                pw[it] = *(const float4*)(W + (size_t)(k0 + 32 + wr[it]) * HD + wc[it]);
            }
        }

#pragma unroll
        for (int ks = 0; ks < 4; ++ks) {
            const int kb = ks * 8;
            unsigned int a0 = __float_as_uint(Xs[mrow + g    ][kb + tig    ]);
            unsigned int a1 = __float_as_uint(Xs[mrow + g + 8][kb + tig    ]);
            unsigned int a2 = __float_as_uint(Xs[mrow + g    ][kb + tig + 4]);
            unsigned int a3 = __float_as_uint(Xs[mrow + g + 8][kb + tig + 4]);
#pragma unroll
            for (int nt = 0; nt < 8; ++nt) {
                unsigned int b0 = __float_as_uint(Ws[kb + tig    ][nt * 8 + g]);
                unsigned int b1 = __float_as_uint(Ws[kb + tig + 4][nt * 8 + g]);
                asm volatile(
                    "mma.sync.aligned.m16n8k8.row.col.f32.tf32.tf32.f32 "
                    "{%0,%1,%2,%3}, {%4,%5,%6,%7}, {%8,%9}, {%0,%1,%2,%3};"
                    : "+f"(c[nt][0]), "+f"(c[nt][1]), "+f"(c[nt][2]), "+f"(c[nt][3])
                    : "r"(a0), "r"(a1), "r"(a2), "r"(a3), "r"(b0), "r"(b1));
            }
        }
        __syncthreads();

        if (has_next) {
#pragma unroll
            for (int it = 0; it < 4; ++it) {
                float4 v = px[it];
                *(float4*)&Xs[xr[it]][xc[it]] =
                    make_float4(to_tf32(v.x), to_tf32(v.y), to_tf32(v.z), to_tf32(v.w));
                v = pw[it];
                *(float4*)&Ws[wr[it]][wc[it]] =
                    make_float4(to_tf32(v.x), to_tf32(v.y), to_tf32(v.z), to_tf32(v.w));
            }
            __syncthreads();
        }
    }

    // epilogue: c layout — c0:(g, 2tig) c1:(g, 2tig+1) c2:(g+8, 2tig) c3:(g+8, 2tig+1)
    const int row0 = m0 + mrow + g;
#pragma unroll
    for (int nt = 0; nt < 8; ++nt) {
        const int col = nt * 8 + 2 * tig;
        *(float2*)&out[(size_t)row0       * HD + col] = make_float2(c[nt][0], c[nt][1]);
        *(float2*)&out[(size_t)(row0 + 8) * HD + col] = make_float2(c[nt][2], c[nt][3]);
    }
}

// ============================================================================
// Kernel 2: attention partial (flash-style, one key chunk per block).
// Double-buffered K/V tiles -> one __syncthreads per 16-key tile.
// grid = (MAXCH, NQT, BATCH), 128 threads; thread t owns one query row.
// ============================================================================
__global__ __launch_bounds__(128) void attn_partial() {
    const int ch    = blockIdx.x;
    const int qtile = blockIdx.y;
    const int b     = blockIdx.z;
    const int nch   = ((qtile + 1) * TQ + CHUNK - 1) / CHUNK;
    if (ch >= nch) return;

    const int t   = threadIdx.x;
    const int qr  = qtile * TQ + t;
    const int row = b * SEQ + qr;

    __shared__ float Ks[2][TK][HD];
    __shared__ float Vs[2][TK][HD];

    float q[HD];
    {
        const float4* qp = (const float4*)(g_q + (size_t)row * HD);
#pragma unroll
        for (int i = 0; i < 16; ++i) {
            float4 v4 = qp[i];
            q[4 * i + 0] = v4.x * SCALE; q[4 * i + 1] = v4.y * SCALE;
            q[4 * i + 2] = v4.z * SCALE; q[4 * i + 3] = v4.w * SCALE;
        }
    }

    float o[HD];
#pragma unroll
    for (int d = 0; d < HD; ++d) o[d] = 0.f;
    float m = __int_as_float(0xff800000);
    float l = 0.f;

    const int c0     = ch * CHUNK;
    const int c1     = min(c0 + CHUNK, (qtile + 1) * TQ);
    const int ntiles = (c1 - c0) / TK;

    // loader: 128 threads x 2 float4 -> one 16x64 tile per array
    const int e0  = t * 2;
    const int lr0 = e0 >> 4,       lc0 = (e0 & 15) * 4;
    const int lr1 = (e0 + 1) >> 4, lc1 = ((e0 + 1) & 15) * 4;

    // preload tile 0 into buffer 0
    {
        const size_t gb = (size_t)(b * SEQ + c0) * HD;
        *(float4*)&Ks[0][lr0][lc0] = *(const float4*)(g_k + gb + lr0 * HD + lc0);
        *(float4*)&Ks[0][lr1][lc1] = *(const float4*)(g_k + gb + lr1 * HD + lc1);
        *(float4*)&Vs[0][lr0][lc0] = *(const float4*)(g_v + gb + lr0 * HD + lc0);
        *(float4*)&Vs[0][lr1][lc1] = *(const float4*)(g_v + gb + lr1 * HD + lc1);
    }
    __syncthreads();

    for (int ti = 0; ti < ntiles; ++ti) {
        const int cur = ti & 1;
        const int k0  = c0 + ti * TK;

        if (ti + 1 < ntiles) {   // issue next tile's loads before compute
            const int nxt = cur ^ 1;
            const size_t gb = (size_t)(b * SEQ + k0 + TK) * HD;
            *(float4*)&Ks[nxt][lr0][lc0] = *(const float4*)(g_k + gb + lr0 * HD + lc0);
            *(float4*)&Ks[nxt][lr1][lc1] = *(const float4*)(g_k + gb + lr1 * HD + lc1);
            *(float4*)&Vs[nxt][lr0][lc0] = *(const float4*)(g_v + gb + lr0 * HD + lc0);
            *(float4*)&Vs[nxt][lr1][lc1] = *(const float4*)(g_v + gb + lr1 * HD + lc1);
        }

        float s[TK];
#pragma unroll
        for (int j = 0; j < TK; ++j) {
            float acc = 0.f;
#pragma unroll
            for (int d4 = 0; d4 < 16; ++d4) {
                float4 kk = *(float4*)&Ks[cur][j][d4 * 4];
                acc += q[4 * d4 + 0] * kk.x + q[4 * d4 + 1] * kk.y
                     + q[4 * d4 + 2] * kk.z + q[4 * d4 + 3] * kk.w;
            }
            s[j] = (k0 + j <= qr) ? acc : __int_as_float(0xff800000);
        }

        float mt = m;
#pragma unroll
        for (int j = 0; j < TK; ++j) mt = fmaxf(mt, s[j]);

        const float corr = __expf(m - mt);   // 0 on first tile
        l *= corr;
#pragma unroll
        for (int d = 0; d < HD; ++d) o[d] *= corr;

#pragma unroll
        for (int j = 0; j < TK; ++j) {
            const float p = __expf(s[j] - mt);
            l += p;
#pragma unroll
            for (int d4 = 0; d4 < 16; ++d4) {
                float4 vv = *(float4*)&Vs[cur][j][d4 * 4];
                o[4 * d4 + 0] += p * vv.x; o[4 * d4 + 1] += p * vv.y;
                o[4 * d4 + 2] += p * vv.z; o[4 * d4 + 3] += p * vv.w;
            }
        }
        m = mt;
        __syncthreads();   // one barrier per tile
    }

    const int part = (b * NQT + qtile) * MAXCH + ch;
    float* po = g_po + (size_t)part * TQ * HD;
#pragma unroll
    for (int d = 0; d < HD; ++d) po[d * TQ + t] = o[d];
    g_pm[part * TQ + t] = m;
    g_pl[part * TQ + t] = l;
}

// ============================================================================
// Kernel 3: combine partials across key chunks and normalize.
// ============================================================================
__global__ __launch_bounds__(128) void attn_combine(float* __restrict__ out) {
    const int qtile = blockIdx.x;
    const int b     = blockIdx.y;
    const int t     = threadIdx.x;
    const int nch   = ((qtile + 1) * TQ + CHUNK - 1) / CHUNK;
    const int qr    = qtile * TQ + t;
    const int pbase = (b * NQT + qtile) * MAXCH;

    float M = __int_as_float(0xff800000);
    for (int c = 0; c < nch; ++c)
        M = fmaxf(M, g_pm[(pbase + c) * TQ + t]);

    float L = 0.f;
    float o[HD];
#pragma unroll
    for (int d = 0; d < HD; ++d) o[d] = 0.f;

    for (int c = 0; c < nch; ++c) {
        const int part = pbase + c;
        const float w  = __expf(g_pm[part * TQ + t] - M);
        L += g_pl[part * TQ + t] * w;
        const float* po = g_po + (size_t)part * TQ * HD;
#pragma unroll
        for (int d = 0; d < HD; ++d) o[d] += w * po[d * TQ + t];
    }

    const float inv = 1.f / L;
    float4* op = (float4*)(out + (size_t)(b * SEQ + qr) * HD);
#pragma unroll
    for (int i = 0; i < 16; ++i)
        op[i] = make_float4(o[4 * i + 0] * inv, o[4 * i + 1] * inv,
                            o[4 * i + 2] * inv, o[4 * i + 3] * inv);
}

// ============================================================================
// Launch
// ============================================================================
extern "C" void kernel_launch(void* const* d_in, const int* in_sizes, int n_in,
                              void* d_out, int out_size) {
    (void)in_sizes; (void)n_in; (void)out_size;
    const float* x  = (const float*)d_in[0];
    const float* Wq = (const float*)d_in[1];
    const float* Wk = (const float*)d_in[2];
    const float* Wv = (const float*)d_in[3];
    float* out = (float*)d_out;

    qkv_tf32    <<<dim3(ROWS / 64, 3), 128>>>(x, Wq, Wk, Wv);
    attn_partial<<<dim3(MAXCH, NQT, BATCH), 128>>>();
    attn_combine<<<dim3(NQT, BATCH), 128>>>(out);
}

// round 8
// speedup vs baseline: 2.0962x; 1.6348x over previous
#include <cuda_runtime.h>
#include <cuda_bf16.h>
#include <math.h>
#include <stdint.h>

#define EMB   1024
#define HD    64
#define BATCH 4
#define SEQ   2048
#define ROWS  (BATCH * SEQ)       // 8192
#define SCALE 0.03125f            // 1/sqrt(1024)

// attention tiling
#define TQ    64                  // queries per block (4 warps x 16 rows)
#define NQT   (SEQ / TQ)          // 32
#define KCH   512                 // keys per split chunk
#define MAXCH (SEQ / KCH)         // 4
#define KT    64                  // keys per inner tile
#define NPARTS (BATCH * NQT * MAXCH)   // 512

// ---------------- scratch (no allocations allowed) ----------------
__device__ float g_q[ROWS * HD];
__device__ float g_k[ROWS * HD];
__device__ float g_v[ROWS * HD];
__device__ float g_wp[3 * 128 * 32 * 16];           // prepacked W fragments (tf32)
__device__ float g_po[(size_t)NPARTS * TQ * HD];    // partial O [part][q][d]
__device__ float g_pm[NPARTS * TQ];
__device__ float g_pl[NPARTS * TQ];

__device__ __forceinline__ float to_tf32(float f) {
    unsigned int u;
    asm("cvt.rna.tf32.f32 %0, %1;" : "=r"(u) : "f"(f));
    return __uint_as_float(u);
}

#define MMA_TF32(C, A0, A1, A2, A3, B0, B1)                                   \
    asm volatile(                                                             \
        "mma.sync.aligned.m16n8k8.row.col.f32.tf32.tf32.f32 "                 \
        "{%0,%1,%2,%3}, {%4,%5,%6,%7}, {%8,%9}, {%0,%1,%2,%3};"               \
        : "+f"((C)[0]), "+f"((C)[1]), "+f"((C)[2]), "+f"((C)[3])              \
        : "r"(A0), "r"(A1), "r"(A2), "r"(A3), "r"(B0), "r"(B1))

// ============================================================================
// Kernel 0: prepack W fragments into gmem, tf32-converted.
// Layout: g_wp[mi][kk(0..127)][lane(0..31)][e(0..15)],
//   lane = g*4+tig, e = nt*2+slot,
//   value = tf32(W[kk*8 + tig + slot*4][nt*8 + g])
// ============================================================================
__global__ __launch_bounds__(256) void prepack(const float* __restrict__ Wq,
                                               const float* __restrict__ Wk,
                                               const float* __restrict__ Wv) {
    int idx = blockIdx.x * 256 + threadIdx.x;
    if (idx >= 3 * 128 * 32 * 16) return;
    int e    = idx & 15;
    int lane = (idx >> 4) & 31;
    int kk   = (idx >> 9) & 127;
    int mi   = idx >> 16;
    int g = lane >> 2, tig = lane & 3;
    int nt = e >> 1, slot = e & 1;
    const float* W = (mi == 0) ? Wq : (mi == 1 ? Wk : Wv);
    float v = W[(size_t)(kk * 8 + tig + slot * 4) * HD + nt * 8 + g];
    g_wp[idx] = to_tf32(v);
}

// ============================================================================
// Kernel 1: QKV projection via tf32 mma. B fragments streamed from g_wp (L2).
// BM=64, BK=32, 128 threads (4 warps x 16 rows). grid = (128, 3).
// ============================================================================
__global__ __launch_bounds__(128) void qkv_tf32(const float* __restrict__ x) {
    const int mi = blockIdx.y;
    float* out = (mi == 0) ? g_q : (mi == 1 ? g_k : g_v);

    __shared__ float Xs[64][36];   // [m][k], pad 4 -> conflict-free frag loads

    const int tid  = threadIdx.x;
    const int lane = tid & 31;
    const int warp = tid >> 5;
    const int g    = lane >> 2;
    const int tig  = lane & 3;
    const int m0   = blockIdx.x * 64;

    int xr[4], xc[4];
#pragma unroll
    for (int it = 0; it < 4; ++it) {
        int idx = it * 128 + tid;
        xr[it] = idx >> 3;  xc[it] = (idx & 7) * 4;   // 64x32 tile
    }

    float c[8][4];
#pragma unroll
    for (int nt = 0; nt < 8; ++nt)
#pragma unroll
        for (int i = 0; i < 4; ++i) c[nt][i] = 0.f;

    float4 px[4];
#pragma unroll
    for (int it = 0; it < 4; ++it)
        px[it] = *(const float4*)(x + (size_t)(m0 + xr[it]) * EMB + xc[it]);
#pragma unroll
    for (int it = 0; it < 4; ++it) {
        float4 v = px[it];
        *(float4*)&Xs[xr[it]][xc[it]] =
            make_float4(to_tf32(v.x), to_tf32(v.y), to_tf32(v.z), to_tf32(v.w));
    }
    __syncthreads();

    const int mrow = warp * 16;

    for (int k0 = 0; k0 < EMB; k0 += 32) {
        const bool hn = (k0 + 32 < EMB);
        if (hn) {
#pragma unroll
            for (int it = 0; it < 4; ++it)
                px[it] = *(const float4*)(x + (size_t)(m0 + xr[it]) * EMB + k0 + 32 + xc[it]);
        }

#pragma unroll
        for (int ks = 0; ks < 4; ++ks) {
            const int kk = (k0 >> 3) + ks;
            const float4* wp4 = (const float4*)(g_wp + ((((size_t)mi * 128) + kk) * 32 + lane) * 16);
            float bf[16];
            *(float4*)&bf[0]  = wp4[0];
            *(float4*)&bf[4]  = wp4[1];
            *(float4*)&bf[8]  = wp4[2];
            *(float4*)&bf[12] = wp4[3];

            const int kb = ks * 8;
            unsigned int a0 = __float_as_uint(Xs[mrow + g    ][kb + tig    ]);
            unsigned int a1 = __float_as_uint(Xs[mrow + g + 8][kb + tig    ]);
            unsigned int a2 = __float_as_uint(Xs[mrow + g    ][kb + tig + 4]);
            unsigned int a3 = __float_as_uint(Xs[mrow + g + 8][kb + tig + 4]);
#pragma unroll
            for (int nt = 0; nt < 8; ++nt) {
                unsigned int b0 = __float_as_uint(bf[nt * 2]);
                unsigned int b1 = __float_as_uint(bf[nt * 2 + 1]);
                MMA_TF32(c[nt], a0, a1, a2, a3, b0, b1);
            }
        }
        __syncthreads();
        if (hn) {
#pragma unroll
            for (int it = 0; it < 4; ++it) {
                float4 v = px[it];
                *(float4*)&Xs[xr[it]][xc[it]] =
                    make_float4(to_tf32(v.x), to_tf32(v.y), to_tf32(v.z), to_tf32(v.w));
            }
            __syncthreads();
        }
    }

    // epilogue: round to tf32 so attention operands are pre-rounded
    const int row0 = m0 + mrow + g;
#pragma unroll
    for (int nt = 0; nt < 8; ++nt) {
        const int col = nt * 8 + 2 * tig;
        *(float2*)&out[(size_t)row0       * HD + col] =
            make_float2(to_tf32(c[nt][0]), to_tf32(c[nt][1]));
        *(float2*)&out[(size_t)(row0 + 8) * HD + col] =
            make_float2(to_tf32(c[nt][2]), to_tf32(c[nt][3]));
    }
}

// ============================================================================
// Kernel 2: flash attention partial via tf32 mma.
// Block = 64 q rows (4 warps x 16), one 512-key chunk; key tiles of 64.
// grid = (MAXCH, NQT, BATCH), 128 threads.
// KP smem doubles as K tile (QK phase) then P tile (PV phase).
// ============================================================================
__global__ __launch_bounds__(128) void attn_mma() {
    const int ch = blockIdx.x, qt = blockIdx.y, b = blockIdx.z;
    const int kstart = ch * KCH;
    const int kend   = min(kstart + KCH, (qt + 1) * TQ);
    if (kstart >= kend) return;

    const int tid  = threadIdx.x;
    const int lane = tid & 31;
    const int warp = tid >> 5;
    const int g    = lane >> 2;
    const int tig  = lane & 3;
    const int w16  = warp * 16;
    const int qw0  = qt * TQ + w16;      // warp's first global q row

    __shared__ float KP[64][68];         // K tile, then P tile (per-warp rows)
    __shared__ float Vp[64][72];

    // Q fragments (q already tf32-grid; *2^-5 is exact)
    float a[8][4];
    {
        const float* qb = g_q + (size_t)(b * SEQ + qw0) * HD;
#pragma unroll
        for (int ks = 0; ks < 8; ++ks) {
            a[ks][0] = qb[(size_t)g       * HD + ks * 8 + tig    ] * SCALE;
            a[ks][1] = qb[(size_t)(g + 8) * HD + ks * 8 + tig    ] * SCALE;
            a[ks][2] = qb[(size_t)g       * HD + ks * 8 + tig + 4] * SCALE;
            a[ks][3] = qb[(size_t)(g + 8) * HD + ks * 8 + tig + 4] * SCALE;
        }
    }

    float oc[8][4];
#pragma unroll
    for (int nt = 0; nt < 8; ++nt)
#pragma unroll
        for (int i = 0; i < 4; ++i) oc[nt][i] = 0.f;
    float m0r = -1e30f, m1r = -1e30f, l0 = 0.f, l1 = 0.f;

    const int nkt = (kend - kstart) / KT;

    for (int t = 0; t < nkt; ++t) {
        const int kt0 = kstart + t * KT;
        __syncthreads();   // previous tile's KP(P)/Vp readers done
        // stage K, V (values already tf32-grid)
#pragma unroll
        for (int i = 0; i < 8; ++i) {
            const int e = i * 128 + tid;
            const int row = e >> 4, c4 = (e & 15) * 4;
            const size_t gb = (size_t)(b * SEQ + kt0 + row) * HD + c4;
            *(float4*)&KP[row][c4] = *(const float4*)(g_k + gb);
            *(float4*)&Vp[row][c4] = *(const float4*)(g_v + gb);
        }
        __syncthreads();

        // S = Q @ K^T
        float s[8][4];
#pragma unroll
        for (int nt = 0; nt < 8; ++nt)
#pragma unroll
            for (int i = 0; i < 4; ++i) s[nt][i] = 0.f;
#pragma unroll
        for (int ks = 0; ks < 8; ++ks) {
            unsigned int a0 = __float_as_uint(a[ks][0]);
            unsigned int a1 = __float_as_uint(a[ks][1]);
            unsigned int a2 = __float_as_uint(a[ks][2]);
            unsigned int a3 = __float_as_uint(a[ks][3]);
#pragma unroll
            for (int nt = 0; nt < 8; ++nt) {
                unsigned int b0 = __float_as_uint(KP[nt * 8 + g][ks * 8 + tig    ]);
                unsigned int b1 = __float_as_uint(KP[nt * 8 + g][ks * 8 + tig + 4]);
                MMA_TF32(s[nt], a0, a1, a2, a3, b0, b1);
            }
        }
        __syncthreads();   // all warps done reading K from KP

        // causal mask
        if (kt0 + KT - 1 > qw0) {
#pragma unroll
            for (int nt = 0; nt < 8; ++nt) {
                const int col = kt0 + nt * 8 + 2 * tig;
                if (col     > qw0 + g)     s[nt][0] = -1e30f;
                if (col + 1 > qw0 + g)     s[nt][1] = -1e30f;
                if (col     > qw0 + g + 8) s[nt][2] = -1e30f;
                if (col + 1 > qw0 + g + 8) s[nt][3] = -1e30f;
            }
        }

        // online softmax
        float mx0 = -1e30f, mx1 = -1e30f;
#pragma unroll
        for (int nt = 0; nt < 8; ++nt) {
            mx0 = fmaxf(mx0, fmaxf(s[nt][0], s[nt][1]));
            mx1 = fmaxf(mx1, fmaxf(s[nt][2], s[nt][3]));
        }
        mx0 = fmaxf(mx0, __shfl_xor_sync(0xffffffffu, mx0, 1));
        mx0 = fmaxf(mx0, __shfl_xor_sync(0xffffffffu, mx0, 2));
        mx1 = fmaxf(mx1, __shfl_xor_sync(0xffffffffu, mx1, 1));
        mx1 = fmaxf(mx1, __shfl_xor_sync(0xffffffffu, mx1, 2));

        const float mn0 = fmaxf(m0r, mx0), mn1 = fmaxf(m1r, mx1);
        const float corr0 = __expf(m0r - mn0), corr1 = __expf(m1r - mn1);

        float sum0 = 0.f, sum1 = 0.f;
#pragma unroll
        for (int nt = 0; nt < 8; ++nt) {
            float p0 = to_tf32(__expf(s[nt][0] - mn0));
            float p1 = to_tf32(__expf(s[nt][1] - mn0));
            float p2 = to_tf32(__expf(s[nt][2] - mn1));
            float p3 = to_tf32(__expf(s[nt][3] - mn1));
            sum0 += p0 + p1;
            sum1 += p2 + p3;
            *(float2*)&KP[w16 + g    ][nt * 8 + 2 * tig] = make_float2(p0, p1);
            *(float2*)&KP[w16 + g + 8][nt * 8 + 2 * tig] = make_float2(p2, p3);
        }
        sum0 += __shfl_xor_sync(0xffffffffu, sum0, 1);
        sum0 += __shfl_xor_sync(0xffffffffu, sum0, 2);
        sum1 += __shfl_xor_sync(0xffffffffu, sum1, 1);
        sum1 += __shfl_xor_sync(0xffffffffu, sum1, 2);

        l0 = l0 * corr0 + sum0;
        l1 = l1 * corr1 + sum1;
        m0r = mn0; m1r = mn1;
#pragma unroll
        for (int nt = 0; nt < 8; ++nt) {
            oc[nt][0] *= corr0; oc[nt][1] *= corr0;
            oc[nt][2] *= corr1; oc[nt][3] *= corr1;
        }
        __syncwarp();   // own warp's P stores visible to own warp's loads

        // O += P @ V
#pragma unroll
        for (int ks = 0; ks < 8; ++ks) {
            unsigned int p0 = __float_as_uint(KP[w16 + g    ][ks * 8 + tig    ]);
            unsigned int p1 = __float_as_uint(KP[w16 + g + 8][ks * 8 + tig    ]);
            unsigned int p2 = __float_as_uint(KP[w16 + g    ][ks * 8 + tig + 4]);
            unsigned int p3 = __float_as_uint(KP[w16 + g + 8][ks * 8 + tig + 4]);
#pragma unroll
            for (int nt = 0; nt < 8; ++nt) {
                unsigned int b0 = __float_as_uint(Vp[ks * 8 + tig    ][nt * 8 + g]);
                unsigned int b1 = __float_as_uint(Vp[ks * 8 + tig + 4][nt * 8 + g]);
                MMA_TF32(oc[nt], p0, p1, p2, p3, b0, b1);
            }
        }
    }

    // write partials
    const int part = (b * NQT + qt) * MAXCH + ch;
    float* po = g_po + (size_t)part * TQ * HD;
#pragma unroll
    for (int nt = 0; nt < 8; ++nt) {
        const int col = nt * 8 + 2 * tig;
        *(float2*)&po[(size_t)(w16 + g)     * HD + col] = make_float2(oc[nt][0], oc[nt][1]);
        *(float2*)&po[(size_t)(w16 + g + 8) * HD + col] = make_float2(oc[nt][2], oc[nt][3]);
    }
    g_pm[part * TQ + w16 + g]     = m0r;   // same value across tig: benign
    g_pm[part * TQ + w16 + g + 8] = m1r;
    g_pl[part * TQ + w16 + g]     = l0;
    g_pl[part * TQ + w16 + g + 8] = l1;
}

// ============================================================================
// Kernel 3: combine partials and normalize. grid = (NQT, BATCH), 64 threads.
// ============================================================================
__global__ __launch_bounds__(64) void attn_combine(float* __restrict__ out) {
    const int qt = blockIdx.x, b = blockIdx.y, t = threadIdx.x;
    const int nch   = ((qt + 1) * TQ + KCH - 1) / KCH;
    const int pbase = (b * NQT + qt) * MAXCH;

    float M = -1e30f;
    for (int c = 0; c < nch; ++c)
        M = fmaxf(M, g_pm[(pbase + c) * TQ + t]);

    float L = 0.f;
    float o[HD];
#pragma unroll
    for (int d = 0; d < HD; ++d) o[d] = 0.f;

    for (int c = 0; c < nch; ++c) {
        const int part = pbase + c;
        const float w = __expf(g_pm[part * TQ + t] - M);
        L += g_pl[part * TQ + t] * w;
        const float4* po4 = (const float4*)(g_po + ((size_t)part * TQ + t) * HD);
#pragma unroll
        for (int d4 = 0; d4 < 16; ++d4) {
            float4 v = po4[d4];
            o[4 * d4 + 0] += w * v.x; o[4 * d4 + 1] += w * v.y;
            o[4 * d4 + 2] += w * v.z; o[4 * d4 + 3] += w * v.w;
        }
    }

    const float inv = 1.f / L;
    float4* op = (float4*)(out + (size_t)(b * SEQ + qt * TQ + t) * HD);
#pragma unroll
    for (int i = 0; i < 16; ++i)
        op[i] = make_float4(o[4 * i + 0] * inv, o[4 * i + 1] * inv,
                            o[4 * i + 2] * inv, o[4 * i + 3] * inv);
}

// ============================================================================
// Launch
// ============================================================================
extern "C" void kernel_launch(void* const* d_in, const int* in_sizes, int n_in,
                              void* d_out, int out_size) {
    (void)in_sizes; (void)n_in; (void)out_size;
    const float* x  = (const float*)d_in[0];
    const float* Wq = (const float*)d_in[1];
    const float* Wk = (const float*)d_in[2];
    const float* Wv = (const float*)d_in[3];
    float* out = (float*)d_out;

    prepack     <<<768, 256>>>(Wq, Wk, Wv);
    qkv_tf32    <<<dim3(ROWS / 64, 3), 128>>>(x);
    attn_mma    <<<dim3(MAXCH, NQT, BATCH), 128>>>();
    attn_combine<<<dim3(NQT, BATCH), 64>>>(out);
}

// round 9
// speedup vs baseline: 2.2658x; 1.0809x over previous
#include <cuda_runtime.h>
#include <cuda_bf16.h>
#include <math.h>
#include <stdint.h>

#define EMB   1024
#define HD    64
#define BATCH 4
#define SEQ   2048
#define ROWS  (BATCH * SEQ)       // 8192
#define SCALE 0.03125f            // 1/sqrt(1024)
#define LOG2E 1.4426950408889634f

// attention tiling
#define TQ    64                  // queries per block (4 warps x 16 rows)
#define NQT   (SEQ / TQ)          // 32
#define KCH   256                 // keys per split chunk
#define MAXCH (SEQ / KCH)         // 8
#define KT    64                  // keys per inner tile
#define NPARTS (BATCH * NQT * MAXCH)   // 1024

// dynamic smem layout for attn: K[2][64][68] then V[2][64][72]
#define KSTR  68
#define VSTR  72
#define KBUF_FLOATS (2 * 64 * KSTR)
#define ATTN_SMEM_BYTES ((KBUF_FLOATS + 2 * 64 * VSTR) * 4)

// ---------------- scratch (no allocations allowed) ----------------
__device__ float g_q[ROWS * HD];
__device__ float g_k[ROWS * HD];
__device__ float g_v[ROWS * HD];
__device__ float g_wp[3 * 128 * 32 * 16];           // prepacked W fragments (tf32)
__device__ float g_po[(size_t)NPARTS * TQ * HD];    // partial O [part][q][d]
__device__ float g_pm[NPARTS * TQ];
__device__ float g_pl[NPARTS * TQ];

__device__ __forceinline__ float to_tf32(float f) {
    unsigned int u;
    asm("cvt.rna.tf32.f32 %0, %1;" : "=r"(u) : "f"(f));
    return __uint_as_float(u);
}

#define MMA_TF32(C, A0, A1, A2, A3, B0, B1)                                   \
    asm volatile(                                                             \
        "mma.sync.aligned.m16n8k8.row.col.f32.tf32.tf32.f32 "                 \
        "{%0,%1,%2,%3}, {%4,%5,%6,%7}, {%8,%9}, {%0,%1,%2,%3};"               \
        : "+f"((C)[0]), "+f"((C)[1]), "+f"((C)[2]), "+f"((C)[3])              \
        : "r"(A0), "r"(A1), "r"(A2), "r"(A3), "r"(B0), "r"(B1))

#define CP_ASYNC16(dst_u32, src_ptr)                                          \
    asm volatile("cp.async.cg.shared.global [%0], [%1], 16;"                  \
                 :: "r"(dst_u32), "l"(src_ptr))
#define CP_COMMIT() asm volatile("cp.async.commit_group;")
#define CP_WAIT(n)  asm volatile("cp.async.wait_group %0;" :: "n"(n))

// ============================================================================
// Kernel 0: prepack W fragments into gmem, tf32-converted.
// g_wp[mi][kk][lane][e]: lane=g*4+tig, e=nt*2+slot,
//   value = tf32(W[kk*8 + tig + slot*4][nt*8 + g])
// ============================================================================
__global__ __launch_bounds__(256) void prepack(const float* __restrict__ Wq,
                                               const float* __restrict__ Wk,
                                               const float* __restrict__ Wv) {
    int idx = blockIdx.x * 256 + threadIdx.x;
    if (idx >= 3 * 128 * 32 * 16) return;
    int e    = idx & 15;
    int lane = (idx >> 4) & 31;
    int kk   = (idx >> 9) & 127;
    int mi   = idx >> 16;
    int g = lane >> 2, tig = lane & 3;
    int nt = e >> 1, slot = e & 1;
    const float* W = (mi == 0) ? Wq : (mi == 1 ? Wk : Wv);
    g_wp[idx] = to_tf32(W[(size_t)(kk * 8 + tig + slot * 4) * HD + nt * 8 + g]);
}

// ============================================================================
// Kernel 1: QKV projection via tf32 mma (B frags streamed from g_wp / L2).
// BM=64, BK=32, 128 threads. grid = (128, 3).
// ============================================================================
__global__ __launch_bounds__(128) void qkv_tf32(const float* __restrict__ x) {
    const int mi = blockIdx.y;
    float* out = (mi == 0) ? g_q : (mi == 1 ? g_k : g_v);

    __shared__ float Xs[64][36];

    const int tid  = threadIdx.x;
    const int lane = tid & 31;
    const int warp = tid >> 5;
    const int g    = lane >> 2;
    const int tig  = lane & 3;
    const int m0   = blockIdx.x * 64;

    int xr[4], xc[4];
#pragma unroll
    for (int it = 0; it < 4; ++it) {
        int idx = it * 128 + tid;
        xr[it] = idx >> 3;  xc[it] = (idx & 7) * 4;
    }

    float c[8][4];
#pragma unroll
    for (int nt = 0; nt < 8; ++nt)
#pragma unroll
        for (int i = 0; i < 4; ++i) c[nt][i] = 0.f;

    float4 px[4];
#pragma unroll
    for (int it = 0; it < 4; ++it)
        px[it] = *(const float4*)(x + (size_t)(m0 + xr[it]) * EMB + xc[it]);
#pragma unroll
    for (int it = 0; it < 4; ++it) {
        float4 v = px[it];
        *(float4*)&Xs[xr[it]][xc[it]] =
            make_float4(to_tf32(v.x), to_tf32(v.y), to_tf32(v.z), to_tf32(v.w));
    }
    __syncthreads();

    const int mrow = warp * 16;

    for (int k0 = 0; k0 < EMB; k0 += 32) {
        const bool hn = (k0 + 32 < EMB);
        if (hn) {
#pragma unroll
            for (int it = 0; it < 4; ++it)
                px[it] = *(const float4*)(x + (size_t)(m0 + xr[it]) * EMB + k0 + 32 + xc[it]);
        }

#pragma unroll
        for (int ks = 0; ks < 4; ++ks) {
            const int kk = (k0 >> 3) + ks;
            const float4* wp4 = (const float4*)(g_wp + ((((size_t)mi * 128) + kk) * 32 + lane) * 16);
            float bf[16];
            *(float4*)&bf[0]  = wp4[0];
            *(float4*)&bf[4]  = wp4[1];
            *(float4*)&bf[8]  = wp4[2];
            *(float4*)&bf[12] = wp4[3];

            const int kb = ks * 8;
            unsigned int a0 = __float_as_uint(Xs[mrow + g    ][kb + tig    ]);
            unsigned int a1 = __float_as_uint(Xs[mrow + g + 8][kb + tig    ]);
            unsigned int a2 = __float_as_uint(Xs[mrow + g    ][kb + tig + 4]);
            unsigned int a3 = __float_as_uint(Xs[mrow + g + 8][kb + tig + 4]);
#pragma unroll
            for (int nt = 0; nt < 8; ++nt) {
                unsigned int b0 = __float_as_uint(bf[nt * 2]);
                unsigned int b1 = __float_as_uint(bf[nt * 2 + 1]);
                MMA_TF32(c[nt], a0, a1, a2, a3, b0, b1);
            }
        }
        __syncthreads();
        if (hn) {
#pragma unroll
            for (int it = 0; it < 4; ++it) {
                float4 v = px[it];
                *(float4*)&Xs[xr[it]][xc[it]] =
                    make_float4(to_tf32(v.x), to_tf32(v.y), to_tf32(v.z), to_tf32(v.w));
            }
            __syncthreads();
        }
    }

    const int row0 = m0 + mrow + g;
#pragma unroll
    for (int nt = 0; nt < 8; ++nt) {
        const int col = nt * 8 + 2 * tig;
        *(float2*)&out[(size_t)row0       * HD + col] =
            make_float2(to_tf32(c[nt][0]), to_tf32(c[nt][1]));
        *(float2*)&out[(size_t)(row0 + 8) * HD + col] =
            make_float2(to_tf32(c[nt][2]), to_tf32(c[nt][3]));
    }
}

// ============================================================================
// Kernel 2: flash attention partial via tf32 mma, cp.async double-buffered.
// Block = 64 q rows (4 warps x 16), one 256-key chunk; key tiles of 64.
// Softmax in log2 domain (EX2 only). grid = (MAXCH, NQT, BATCH), 128 thr.
// ============================================================================
__global__ __launch_bounds__(128) void attn_mma() {
    const int ch = blockIdx.x, qt = blockIdx.y, b = blockIdx.z;
    const int kstart = ch * KCH;
    const int kend   = min(kstart + KCH, (qt + 1) * TQ);
    if (kstart >= kend) return;

    extern __shared__ float sm[];
    float* Kb = sm;                 // [2][64][KSTR]
    float* Vb = sm + KBUF_FLOATS;   // [2][64][VSTR]
    const unsigned smem_k = (unsigned)__cvta_generic_to_shared(Kb);
    const unsigned smem_v = (unsigned)__cvta_generic_to_shared(Vb);

    const int tid  = threadIdx.x;
    const int lane = tid & 31;
    const int warp = tid >> 5;
    const int g    = lane >> 2;
    const int tig  = lane & 3;
    const int w16  = warp * 16;
    const int qw0  = qt * TQ + w16;

    // staging element mapping: 8 float4 per thread per array
    int srow[8], scol[8];
#pragma unroll
    for (int i = 0; i < 8; ++i) {
        int e = i * 128 + tid;
        srow[i] = e >> 4; scol[i] = (e & 15) * 4;
    }
    const int nkt = (kend - kstart) / KT;

    // prefetch tile 0 into buffer 0
#pragma unroll
    for (int i = 0; i < 8; ++i) {
        const size_t gb = (size_t)(b * SEQ + kstart + srow[i]) * HD + scol[i];
        CP_ASYNC16(smem_k + (srow[i] * KSTR + scol[i]) * 4, g_k + gb);
        CP_ASYNC16(smem_v + (srow[i] * VSTR + scol[i]) * 4, g_v + gb);
    }
    CP_COMMIT();

    // Q fragments, scaled into log2 domain (SCALE * log2e)
    float a[8][4];
    {
        const float* qb = g_q + (size_t)(b * SEQ + qw0) * HD;
        const float qs = SCALE * LOG2E;
#pragma unroll
        for (int ks = 0; ks < 8; ++ks) {
            a[ks][0] = qb[(size_t)g       * HD + ks * 8 + tig    ] * qs;
            a[ks][1] = qb[(size_t)(g + 8) * HD + ks * 8 + tig    ] * qs;
            a[ks][2] = qb[(size_t)g       * HD + ks * 8 + tig + 4] * qs;
            a[ks][3] = qb[(size_t)(g + 8) * HD + ks * 8 + tig + 4] * qs;
        }
    }

    float oc[8][4];
#pragma unroll
    for (int nt = 0; nt < 8; ++nt)
#pragma unroll
        for (int i = 0; i < 4; ++i) oc[nt][i] = 0.f;
    float m0r = -1e30f, m1r = -1e30f, l0 = 0.f, l1 = 0.f;

    for (int t = 0; t < nkt; ++t) {
        const int cur = t & 1;
        const int kt0 = kstart + t * KT;
        float* Kc = Kb + cur * 64 * KSTR;
        float* Vc = Vb + cur * 64 * VSTR;

        if (t + 1 < nkt) {   // prefetch next tile into alternate buffer
            const int nxt = cur ^ 1;
#pragma unroll
            for (int i = 0; i < 8; ++i) {
                const size_t gb = (size_t)(b * SEQ + kt0 + KT + srow[i]) * HD + scol[i];
                CP_ASYNC16(smem_k + ((nxt * 64 + srow[i]) * KSTR + scol[i]) * 4, g_k + gb);
                CP_ASYNC16(smem_v + ((nxt * 64 + srow[i]) * VSTR + scol[i]) * 4, g_v + gb);
            }
            CP_COMMIT();
            CP_WAIT(1);
        } else {
            CP_WAIT(0);
        }
        __syncthreads();   // tile t staged for all threads

        // S = Q @ K^T  (log2 domain)
        float s[8][4];
#pragma unroll
        for (int nt = 0; nt < 8; ++nt)
#pragma unroll
            for (int i = 0; i < 4; ++i) s[nt][i] = 0.f;
#pragma unroll
        for (int ks = 0; ks < 8; ++ks) {
            unsigned int a0 = __float_as_uint(a[ks][0]);
            unsigned int a1 = __float_as_uint(a[ks][1]);
            unsigned int a2 = __float_as_uint(a[ks][2]);
            unsigned int a3 = __float_as_uint(a[ks][3]);
#pragma unroll
            for (int nt = 0; nt < 8; ++nt) {
                unsigned int b0 = __float_as_uint(Kc[(nt * 8 + g) * KSTR + ks * 8 + tig    ]);
                unsigned int b1 = __float_as_uint(Kc[(nt * 8 + g) * KSTR + ks * 8 + tig + 4]);
                MMA_TF32(s[nt], a0, a1, a2, a3, b0, b1);
            }
        }
        __syncthreads();   // all warps done reading K before P overwrites it

        // causal mask
        if (kt0 + KT - 1 > qw0) {
#pragma unroll
            for (int nt = 0; nt < 8; ++nt) {
                const int col = kt0 + nt * 8 + 2 * tig;
                if (col     > qw0 + g)     s[nt][0] = -1e30f;
                if (col + 1 > qw0 + g)     s[nt][1] = -1e30f;
                if (col     > qw0 + g + 8) s[nt][2] = -1e30f;
                if (col + 1 > qw0 + g + 8) s[nt][3] = -1e30f;
            }
        }

        // online softmax (log2 domain: exp2 only)
        float mx0 = -1e30f, mx1 = -1e30f;
#pragma unroll
        for (int nt = 0; nt < 8; ++nt) {
            mx0 = fmaxf(mx0, fmaxf(s[nt][0], s[nt][1]));
            mx1 = fmaxf(mx1, fmaxf(s[nt][2], s[nt][3]));
        }
        mx0 = fmaxf(mx0, __shfl_xor_sync(0xffffffffu, mx0, 1));
        mx0 = fmaxf(mx0, __shfl_xor_sync(0xffffffffu, mx0, 2));
        mx1 = fmaxf(mx1, __shfl_xor_sync(0xffffffffu, mx1, 1));
        mx1 = fmaxf(mx1, __shfl_xor_sync(0xffffffffu, mx1, 2));

        const float mn0 = fmaxf(m0r, mx0), mn1 = fmaxf(m1r, mx1);
        const float corr0 = exp2f(m0r - mn0), corr1 = exp2f(m1r - mn1);

        float sum0 = 0.f, sum1 = 0.f;
        float* Pw = Kc;   // P tile lives in current K buffer (per-warp rows)
#pragma unroll
        for (int nt = 0; nt < 8; ++nt) {
            float p0 = to_tf32(exp2f(s[nt][0] - mn0));
            float p1 = to_tf32(exp2f(s[nt][1] - mn0));
            float p2 = to_tf32(exp2f(s[nt][2] - mn1));
            float p3 = to_tf32(exp2f(s[nt][3] - mn1));
            sum0 += p0 + p1;
            sum1 += p2 + p3;
            *(float2*)&Pw[(w16 + g    ) * KSTR + nt * 8 + 2 * tig] = make_float2(p0, p1);
            *(float2*)&Pw[(w16 + g + 8) * KSTR + nt * 8 + 2 * tig] = make_float2(p2, p3);
        }
        sum0 += __shfl_xor_sync(0xffffffffu, sum0, 1);
        sum0 += __shfl_xor_sync(0xffffffffu, sum0, 2);
        sum1 += __shfl_xor_sync(0xffffffffu, sum1, 1);
        sum1 += __shfl_xor_sync(0xffffffffu, sum1, 2);

        l0 = l0 * corr0 + sum0;
        l1 = l1 * corr1 + sum1;
        m0r = mn0; m1r = mn1;
#pragma unroll
        for (int nt = 0; nt < 8; ++nt) {
            oc[nt][0] *= corr0; oc[nt][1] *= corr0;
            oc[nt][2] *= corr1; oc[nt][3] *= corr1;
        }
        __syncwarp();   // own warp's P stores visible to own warp's loads

        // O += P @ V
#pragma unroll
        for (int ks = 0; ks < 8; ++ks) {
            unsigned int p0 = __float_as_uint(Pw[(w16 + g    ) * KSTR + ks * 8 + tig    ]);
            unsigned int p1 = __float_as_uint(Pw[(w16 + g + 8) * KSTR + ks * 8 + tig    ]);
            unsigned int p2 = __float_as_uint(Pw[(w16 + g    ) * KSTR + ks * 8 + tig + 4]);
            unsigned int p3 = __float_as_uint(Pw[(w16 + g + 8) * KSTR + ks * 8 + tig + 4]);
#pragma unroll
            for (int nt = 0; nt < 8; ++nt) {
                unsigned int b0 = __float_as_uint(Vc[(ks * 8 + tig    ) * VSTR + nt * 8 + g]);
                unsigned int b1 = __float_as_uint(Vc[(ks * 8 + tig + 4) * VSTR + nt * 8 + g]);
                MMA_TF32(oc[nt], p0, p1, p2, p3, b0, b1);
            }
        }
        __syncthreads();   // bufs fully consumed before next iter's cp.async
    }

    const int part = (b * NQT + qt) * MAXCH + ch;
    float* po = g_po + (size_t)part * TQ * HD;
#pragma unroll
    for (int nt = 0; nt < 8; ++nt) {
        const int col = nt * 8 + 2 * tig;
        *(float2*)&po[(size_t)(w16 + g)     * HD + col] = make_float2(oc[nt][0], oc[nt][1]);
        *(float2*)&po[(size_t)(w16 + g + 8) * HD + col] = make_float2(oc[nt][2], oc[nt][3]);
    }
    g_pm[part * TQ + w16 + g]     = m0r;   // log2-domain; same across tig
    g_pm[part * TQ + w16 + g + 8] = m1r;
    g_pl[part * TQ + w16 + g]     = l0;
    g_pl[part * TQ + w16 + g + 8] = l1;
}

// ============================================================================
// Kernel 3: combine partials and normalize.
// grid = (NQT, BATCH), 256 threads: thread = (q-row, d-quarter of 16).
// ============================================================================
__global__ __launch_bounds__(256) void attn_combine(float* __restrict__ out) {
    const int qt = blockIdx.x, b = blockIdx.y;
    const int r  = threadIdx.x >> 2;          // q row 0..63
    const int dq = (threadIdx.x & 3) * 16;    // d offset
    const int nch   = ((qt + 1) * TQ + KCH - 1) / KCH;
    const int pbase = (b * NQT + qt) * MAXCH;

    float M = -1e30f;
    for (int c = 0; c < nch; ++c)
        M = fmaxf(M, g_pm[(pbase + c) * TQ + r]);

    float L = 0.f;
    float o[16];
#pragma unroll
    for (int d = 0; d < 16; ++d) o[d] = 0.f;

    for (int c = 0; c < nch; ++c) {
        const int part = pbase + c;
        const float w = exp2f(g_pm[part * TQ + r] - M);   // log2 domain
        L += g_pl[part * TQ + r] * w;
        const float4* po4 = (const float4*)(g_po + ((size_t)part * TQ + r) * HD + dq);
#pragma unroll
        for (int i = 0; i < 4; ++i) {
            float4 v = po4[i];
            o[4 * i + 0] += w * v.x; o[4 * i + 1] += w * v.y;
            o[4 * i + 2] += w * v.z; o[4 * i + 3] += w * v.w;
        }
    }

    const float inv = 1.f / L;
    float4* op = (float4*)(out + (size_t)(b * SEQ + qt * TQ + r) * HD + dq);
#pragma unroll
    for (int i = 0; i < 4; ++i)
        op[i] = make_float4(o[4 * i + 0] * inv, o[4 * i + 1] * inv,
                            o[4 * i + 2] * inv, o[4 * i + 3] * inv);
}

// ============================================================================
// Launch
// ============================================================================
extern "C" void kernel_launch(void* const* d_in, const int* in_sizes, int n_in,
                              void* d_out, int out_size) {
    (void)in_sizes; (void)n_in; (void)out_size;
    const float* x  = (const float*)d_in[0];
    const float* Wq = (const float*)d_in[1];
    const float* Wk = (const float*)d_in[2];
    const float* Wv = (const float*)d_in[3];
    float* out = (float*)d_out;

    static int smem_set = 0;
    if (!smem_set) {
        cudaFuncSetAttribute(attn_mma, cudaFuncAttributeMaxDynamicSharedMemorySize,
                             ATTN_SMEM_BYTES);
        smem_set = 1;
    }

    prepack     <<<768, 256>>>(Wq, Wk, Wv);
    qkv_tf32    <<<dim3(ROWS / 64, 3), 128>>>(x);
    attn_mma    <<<dim3(MAXCH, NQT, BATCH), 128, ATTN_SMEM_BYTES>>>();
    attn_combine<<<dim3(NQT, BATCH), 256>>>(out);
}